// round 1
// baseline (speedup 1.0000x reference)
#include <cuda_runtime.h>

#define NN 100000
#define MM 20000
#define PP 1600000
#define CIN 768
#define HID 128
#define NLAYERS 16
#define NOUT 16
#define EPSV 1e-5f

// ---------------- scratch (device globals; no dynamic allocation) ----------
__device__ float g_x[NN * HID];     // node features (residual stream)
__device__ float g_h[NN * HID];     // post-theta features
__device__ float g_acc[NN * HID];   // edge->vertex accumulation
__device__ float g_xe[MM * HID];    // vertex->edge accumulation
__device__ float g_inv_ce[MM];
__device__ float g_inv_cv[NN];
__device__ int   g_cnt_e[MM];
__device__ int   g_cnt_v[NN];

// ---------------- degree counting ----------------
__global__ void zero_counts_kernel() {
    int i = blockIdx.x * blockDim.x + threadIdx.x;
    if (i < MM) g_cnt_e[i] = 0;
    if (i < NN) g_cnt_v[i] = 0;
}

__global__ void count_kernel(const int* __restrict__ v_idx,
                             const int* __restrict__ e_idx) {
    int i = blockIdx.x * blockDim.x + threadIdx.x;
    if (i < PP) {
        atomicAdd(&g_cnt_e[e_idx[i]], 1);
        atomicAdd(&g_cnt_v[v_idx[i]], 1);
    }
}

__global__ void inv_kernel() {
    int i = blockIdx.x * blockDim.x + threadIdx.x;
    if (i < MM) g_inv_ce[i] = 1.0f / fmaxf((float)g_cnt_e[i], 1.0f);
    if (i < NN) g_inv_cv[i] = 1.0f / fmaxf((float)g_cnt_v[i], 1.0f);
}

// ---------------- encoder GEMM: g_x = X @ W_enc + b_enc --------------------
// BM=64 rows, BN=128 (full), BK=16. 256 threads; 8x4 micro-tile per thread.
__global__ void enc_gemm_kernel(const float* __restrict__ X,
                                const float* __restrict__ W,
                                const float* __restrict__ bias) {
    __shared__ float As[64][20];    // padded BK=16 -> 20
    __shared__ float Bs[16][128];
    int t = threadIdx.x;
    int ty = t >> 5;   // 0..7
    int tx = t & 31;   // 0..31
    int row0 = blockIdx.x * 64;

    float acc[8][4];
#pragma unroll
    for (int i = 0; i < 8; i++)
#pragma unroll
        for (int j = 0; j < 4; j++) acc[i][j] = 0.0f;

    for (int k0 = 0; k0 < CIN; k0 += 16) {
#pragma unroll
        for (int i = 0; i < 4; i++) {
            int idx = t + i * 256;
            int r = idx >> 4, c = idx & 15;
            int row = row0 + r;
            As[r][c] = (row < NN) ? X[row * CIN + k0 + c] : 0.0f;
        }
#pragma unroll
        for (int i = 0; i < 8; i++) {
            int idx = t + i * 256;
            int r = idx >> 7, c = idx & 127;
            Bs[r][c] = W[(k0 + r) * HID + c];
        }
        __syncthreads();
#pragma unroll
        for (int k = 0; k < 16; k++) {
            float a[8];
#pragma unroll
            for (int i = 0; i < 8; i++) a[i] = As[ty * 8 + i][k];
            float4 bv = *(const float4*)&Bs[k][tx * 4];
#pragma unroll
            for (int i = 0; i < 8; i++) {
                acc[i][0] += a[i] * bv.x;
                acc[i][1] += a[i] * bv.y;
                acc[i][2] += a[i] * bv.z;
                acc[i][3] += a[i] * bv.w;
            }
        }
        __syncthreads();
    }

#pragma unroll
    for (int i = 0; i < 8; i++) {
        int row = row0 + ty * 8 + i;
        if (row < NN) {
#pragma unroll
            for (int j = 0; j < 4; j++)
                g_x[row * HID + tx * 4 + j] = acc[i][j] + bias[tx * 4 + j];
        }
    }
}

// ---------------- per-layer: h = relu(LN(x)*g+b) @ W + bb ------------------
__global__ void ln_gemm_kernel(const float* __restrict__ lng,
                               const float* __restrict__ lnb,
                               const float* __restrict__ W,
                               const float* __restrict__ bb) {
    __shared__ float As[64][132];   // normalized+relu'd activations
    __shared__ float Bs[16][128];
    int t = threadIdx.x;
    int ty = t >> 5;
    int tx = t & 31;
    int row0 = blockIdx.x * 64;

    // LN phase: warp ty handles rows ty*8 .. ty*8+7
#pragma unroll
    for (int rr = 0; rr < 8; rr++) {
        int r = ty * 8 + rr;
        int row = row0 + r;
        float4 v = make_float4(0.f, 0.f, 0.f, 0.f);
        if (row < NN) v = *(const float4*)&g_x[row * HID + tx * 4];
        float s  = v.x + v.y + v.z + v.w;
        float sq = v.x * v.x + v.y * v.y + v.z * v.z + v.w * v.w;
#pragma unroll
        for (int off = 16; off > 0; off >>= 1) {
            s  += __shfl_xor_sync(0xffffffffu, s, off);
            sq += __shfl_xor_sync(0xffffffffu, sq, off);
        }
        float mu  = s * (1.0f / 128.0f);
        float var = sq * (1.0f / 128.0f) - mu * mu;
        float rs  = rsqrtf(var + EPSV);
        float vv[4] = {v.x, v.y, v.z, v.w};
#pragma unroll
        for (int j = 0; j < 4; j++) {
            int c = tx * 4 + j;
            float hv = (vv[j] - mu) * rs * lng[c] + lnb[c];
            As[r][c] = fmaxf(hv, 0.0f);
        }
    }
    __syncthreads();

    float acc[8][4];
#pragma unroll
    for (int i = 0; i < 8; i++)
#pragma unroll
        for (int j = 0; j < 4; j++) acc[i][j] = 0.0f;

    for (int k0 = 0; k0 < HID; k0 += 16) {
#pragma unroll
        for (int i = 0; i < 8; i++) {
            int idx = t + i * 256;
            int r = idx >> 7, c = idx & 127;
            Bs[r][c] = W[(k0 + r) * HID + c];
        }
        __syncthreads();
#pragma unroll
        for (int k = 0; k < 16; k++) {
            float a[8];
#pragma unroll
            for (int i = 0; i < 8; i++) a[i] = As[ty * 8 + i][k0 + k];
            float4 bv = *(const float4*)&Bs[k][tx * 4];
#pragma unroll
            for (int i = 0; i < 8; i++) {
                acc[i][0] += a[i] * bv.x;
                acc[i][1] += a[i] * bv.y;
                acc[i][2] += a[i] * bv.z;
                acc[i][3] += a[i] * bv.w;
            }
        }
        __syncthreads();
    }

#pragma unroll
    for (int i = 0; i < 8; i++) {
        int row = row0 + ty * 8 + i;
        if (row < NN) {
#pragma unroll
            for (int j = 0; j < 4; j++)
                g_h[row * HID + tx * 4 + j] = acc[i][j] + bb[tx * 4 + j];
        }
    }
}

// ---------------- zero Xe and acc ----------------
__global__ void zero_xe_acc_kernel() {
    int i = blockIdx.x * blockDim.x + threadIdx.x;   // float4 index
    const float4 z = make_float4(0.f, 0.f, 0.f, 0.f);
    if (i < MM * 32) {
        ((float4*)g_xe)[i] = z;
    } else if (i < (MM + NN) * 32) {
        ((float4*)g_acc)[i - MM * 32] = z;
    }
}

// vectorized global reduction (sm_90+: red.global.add.v4.f32)
__device__ __forceinline__ void red_add_v4(float* dst, float4 v) {
    asm volatile("red.global.add.v4.f32 [%0], {%1,%2,%3,%4};"
                 :: "l"(dst), "f"(v.x), "f"(v.y), "f"(v.z), "f"(v.w)
                 : "memory");
}

// pass 1: Xe[e] += h[v]   (one warp per incidence pair)
__global__ void scatter_ve_kernel(const int* __restrict__ v_idx,
                                  const int* __restrict__ e_idx) {
    int w = (blockIdx.x * blockDim.x + threadIdx.x) >> 5;
    int lane = threadIdx.x & 31;
    if (w >= PP) return;
    int v = __ldg(&v_idx[w]);
    int e = __ldg(&e_idx[w]);
    float4 val = *(const float4*)&g_h[v * HID + lane * 4];
    red_add_v4(&g_xe[e * HID + lane * 4], val);
}

// pass 2: acc[v] += Xe[e] * inv_ce[e]
__global__ void scatter_ev_kernel(const int* __restrict__ v_idx,
                                  const int* __restrict__ e_idx) {
    int w = (blockIdx.x * blockDim.x + threadIdx.x) >> 5;
    int lane = threadIdx.x & 31;
    if (w >= PP) return;
    int v = __ldg(&v_idx[w]);
    int e = __ldg(&e_idx[w]);
    float sc = __ldg(&g_inv_ce[e]);
    float4 val = *(const float4*)&g_xe[e * HID + lane * 4];
    val.x *= sc; val.y *= sc; val.z *= sc; val.w *= sc;
    red_add_v4(&g_acc[v * HID + lane * 4], val);
}

// ---------------- residual update: x += relu(acc * inv_cv) -----------------
__global__ void update_kernel() {
    int i = blockIdx.x * blockDim.x + threadIdx.x;   // float4 index over N*32
    if (i >= NN * 32) return;
    int row = i >> 5;
    float s = g_inv_cv[row];
    float4 a = ((const float4*)g_acc)[i];
    float4 x = ((const float4*)g_x)[i];
    x.x += fmaxf(a.x * s, 0.0f);
    x.y += fmaxf(a.y * s, 0.0f);
    x.z += fmaxf(a.z * s, 0.0f);
    x.w += fmaxf(a.w * s, 0.0f);
    ((float4*)g_x)[i] = x;
}

// ---------------- head: log_softmax(x @ W_out + b_out) ---------------------
__global__ void out_kernel(const float* __restrict__ Wo,
                           const float* __restrict__ bo,
                           float* __restrict__ out) {
    __shared__ float WsT[NOUT][HID];   // transposed: [o][k]
    __shared__ float bs[NOUT];
    int t = threadIdx.x;
    for (int i = t; i < HID * NOUT; i += 256) {
        int k = i >> 4, o = i & 15;
        WsT[o][k] = Wo[i];
    }
    if (t < NOUT) bs[t] = bo[t];
    __syncthreads();

    int w = (blockIdx.x * 256 + t) >> 5;
    int lane = t & 31;
    if (w >= NN) return;
    float4 x = *(const float4*)&g_x[w * HID + lane * 4];

    float r[NOUT];
#pragma unroll
    for (int o = 0; o < NOUT; o++) {
        float4 wv = *(const float4*)&WsT[o][lane * 4];
        float p = x.x * wv.x + x.y * wv.y + x.z * wv.z + x.w * wv.w;
#pragma unroll
        for (int off = 16; off > 0; off >>= 1)
            p += __shfl_xor_sync(0xffffffffu, p, off);
        r[o] = p + bs[o];
    }

    float m = r[0];
#pragma unroll
    for (int o = 1; o < NOUT; o++) m = fmaxf(m, r[o]);
    float sum = 0.0f;
#pragma unroll
    for (int o = 0; o < NOUT; o++) sum += expf(r[o] - m);
    float lse = m + logf(sum);

    if (lane == 0) {
#pragma unroll
        for (int o = 0; o < NOUT; o++)
            out[w * NOUT + o] = r[o] - lse;
    }
}

// ---------------- launcher ----------------
extern "C" void kernel_launch(void* const* d_in, const int* in_sizes, int n_in,
                              void* d_out, int out_size) {
    const float* X     = (const float*)d_in[0];
    const int*   v_idx = (const int*)  d_in[1];
    const int*   e_idx = (const int*)  d_in[2];
    const float* W_enc = (const float*)d_in[3];
    const float* b_enc = (const float*)d_in[4];
    const float* ln_g  = (const float*)d_in[5];
    const float* ln_b  = (const float*)d_in[6];
    const float* Wt    = (const float*)d_in[7];
    const float* bt    = (const float*)d_in[8];
    const float* W_out = (const float*)d_in[9];
    const float* b_out = (const float*)d_in[10];
    float* out = (float*)d_out;

    // degrees
    zero_counts_kernel<<<(NN + 255) / 256, 256>>>();
    count_kernel<<<(PP + 255) / 256, 256>>>(v_idx, e_idx);
    inv_kernel<<<(NN + 255) / 256, 256>>>();

    // encoder
    enc_gemm_kernel<<<(NN + 63) / 64, 256>>>(X, W_enc, b_enc);

    const int scat_blocks = PP / 8;               // 8 warps per block, 1 warp/pair
    const int zero_blocks = ((MM + NN) * 32 + 255) / 256;

    for (int l = 0; l < NLAYERS; l++) {
        zero_xe_acc_kernel<<<zero_blocks, 256>>>();
        ln_gemm_kernel<<<(NN + 63) / 64, 256>>>(ln_g + l * HID, ln_b + l * HID,
                                                Wt + l * HID * HID, bt + l * HID);
        scatter_ve_kernel<<<scat_blocks, 256>>>(v_idx, e_idx);
        scatter_ev_kernel<<<scat_blocks, 256>>>(v_idx, e_idx);
        update_kernel<<<(NN * 32 + 255) / 256, 256>>>();
    }

    out_kernel<<<NN / 8, 256>>>(W_out, b_out, out);
}

// round 2
// speedup vs baseline: 1.9970x; 1.9970x over previous
#include <cuda_runtime.h>

#define NN 100000
#define MM 20000
#define PP 1600000
#define CIN 768
#define HID 128
#define NLAYERS 16
#define NOUT 16
#define EPSV 1e-5f

// ---------------- scratch (device globals; no dynamic allocation) ----------
__device__ float g_x[NN * HID];     // node features (residual stream)
__device__ float g_h[NN * HID];     // post-theta features
__device__ float g_xe[MM * HID];    // per-edge features
__device__ float g_inv_ce[MM];
__device__ float g_inv_cv[NN];
__device__ int   g_cnt_e[MM];
__device__ int   g_cnt_v[NN];
__device__ int   g_off_e[MM + 1];
__device__ int   g_off_v[NN + 1];
__device__ int   g_cur_e[MM];
__device__ int   g_cur_v[NN];
__device__ int   g_csr_ev[PP];      // vertex ids grouped by edge
__device__ int   g_csr_ve[PP];      // edge ids grouped by vertex

// ---------------- degree counting ----------------
__global__ void zero_counts_kernel() {
    int i = blockIdx.x * blockDim.x + threadIdx.x;
    if (i < MM) g_cnt_e[i] = 0;
    if (i < NN) g_cnt_v[i] = 0;
}

__global__ void count_kernel(const int* __restrict__ v_idx,
                             const int* __restrict__ e_idx) {
    int i = blockIdx.x * blockDim.x + threadIdx.x;
    if (i < PP) {
        atomicAdd(&g_cnt_e[e_idx[i]], 1);
        atomicAdd(&g_cnt_v[v_idx[i]], 1);
    }
}

__global__ void inv_kernel() {
    int i = blockIdx.x * blockDim.x + threadIdx.x;
    if (i < MM) g_inv_ce[i] = 1.0f / fmaxf((float)g_cnt_e[i], 1.0f);
    if (i < NN) g_inv_cv[i] = 1.0f / fmaxf((float)g_cnt_v[i], 1.0f);
}

// ---------------- single-block exclusive scan (off[0]=0, off[i+1]=incl) ----
__global__ void scan_kernel(const int* __restrict__ cnt, int* __restrict__ off,
                            int* __restrict__ cur, int n) {
    __shared__ int warp_sums[32];
    __shared__ int s_carry;
    int t = threadIdx.x;
    int lane = t & 31, wid = t >> 5;
    if (t == 0) { s_carry = 0; off[0] = 0; }
    __syncthreads();
    for (int base = 0; base < n; base += 1024) {
        int i = base + t;
        int v = (i < n) ? cnt[i] : 0;
        if (i < n) cur[i] = 0;
        int x = v;
#pragma unroll
        for (int d = 1; d < 32; d <<= 1) {
            int y = __shfl_up_sync(0xffffffffu, x, d);
            if (lane >= d) x += y;
        }
        if (lane == 31) warp_sums[wid] = x;
        __syncthreads();
        if (wid == 0) {
            int ws = warp_sums[lane];
#pragma unroll
            for (int d = 1; d < 32; d <<= 1) {
                int y = __shfl_up_sync(0xffffffffu, ws, d);
                if (lane >= d) ws += y;
            }
            warp_sums[lane] = ws;
        }
        __syncthreads();
        int incl = x + (wid > 0 ? warp_sums[wid - 1] : 0) + s_carry;
        if (i < n) off[i + 1] = incl;
        __syncthreads();
        if (t == 1023) s_carry = incl;
        __syncthreads();
    }
}

// ---------------- CSR fill (counting sort placement) ----------------------
__global__ void fill_csr_kernel(const int* __restrict__ v_idx,
                                const int* __restrict__ e_idx) {
    int i = blockIdx.x * blockDim.x + threadIdx.x;
    if (i >= PP) return;
    int v = v_idx[i];
    int e = e_idx[i];
    int pe = atomicAdd(&g_cur_e[e], 1);
    g_csr_ev[g_off_e[e] + pe] = v;
    int pv = atomicAdd(&g_cur_v[v], 1);
    g_csr_ve[g_off_v[v] + pv] = e;
}

// ---------------- encoder GEMM: g_x = X @ W_enc + b_enc --------------------
__global__ void enc_gemm_kernel(const float* __restrict__ X,
                                const float* __restrict__ W,
                                const float* __restrict__ bias) {
    __shared__ float As[64][20];
    __shared__ float Bs[16][128];
    int t = threadIdx.x;
    int ty = t >> 5;
    int tx = t & 31;
    int row0 = blockIdx.x * 64;

    float acc[8][4];
#pragma unroll
    for (int i = 0; i < 8; i++)
#pragma unroll
        for (int j = 0; j < 4; j++) acc[i][j] = 0.0f;

    for (int k0 = 0; k0 < CIN; k0 += 16) {
#pragma unroll
        for (int i = 0; i < 4; i++) {
            int idx = t + i * 256;
            int r = idx >> 4, c = idx & 15;
            int row = row0 + r;
            As[r][c] = (row < NN) ? X[row * CIN + k0 + c] : 0.0f;
        }
#pragma unroll
        for (int i = 0; i < 8; i++) {
            int idx = t + i * 256;
            int r = idx >> 7, c = idx & 127;
            Bs[r][c] = W[(k0 + r) * HID + c];
        }
        __syncthreads();
#pragma unroll
        for (int k = 0; k < 16; k++) {
            float a[8];
#pragma unroll
            for (int i = 0; i < 8; i++) a[i] = As[ty * 8 + i][k];
            float4 bv = *(const float4*)&Bs[k][tx * 4];
#pragma unroll
            for (int i = 0; i < 8; i++) {
                acc[i][0] += a[i] * bv.x;
                acc[i][1] += a[i] * bv.y;
                acc[i][2] += a[i] * bv.z;
                acc[i][3] += a[i] * bv.w;
            }
        }
        __syncthreads();
    }

#pragma unroll
    for (int i = 0; i < 8; i++) {
        int row = row0 + ty * 8 + i;
        if (row < NN) {
#pragma unroll
            for (int j = 0; j < 4; j++)
                g_x[row * HID + tx * 4 + j] = acc[i][j] + bias[tx * 4 + j];
        }
    }
}

// ---------------- per-layer: h = relu(LN(x)*g+b) @ W + bb ------------------
__global__ void ln_gemm_kernel(const float* __restrict__ lng,
                               const float* __restrict__ lnb,
                               const float* __restrict__ W,
                               const float* __restrict__ bb) {
    __shared__ float As[64][132];
    __shared__ float Bs[16][128];
    int t = threadIdx.x;
    int ty = t >> 5;
    int tx = t & 31;
    int row0 = blockIdx.x * 64;

#pragma unroll
    for (int rr = 0; rr < 8; rr++) {
        int r = ty * 8 + rr;
        int row = row0 + r;
        float4 v = make_float4(0.f, 0.f, 0.f, 0.f);
        if (row < NN) v = *(const float4*)&g_x[row * HID + tx * 4];
        float s  = v.x + v.y + v.z + v.w;
        float sq = v.x * v.x + v.y * v.y + v.z * v.z + v.w * v.w;
#pragma unroll
        for (int off = 16; off > 0; off >>= 1) {
            s  += __shfl_xor_sync(0xffffffffu, s, off);
            sq += __shfl_xor_sync(0xffffffffu, sq, off);
        }
        float mu  = s * (1.0f / 128.0f);
        float var = sq * (1.0f / 128.0f) - mu * mu;
        float rs  = rsqrtf(var + EPSV);
        float vv[4] = {v.x, v.y, v.z, v.w};
#pragma unroll
        for (int j = 0; j < 4; j++) {
            int c = tx * 4 + j;
            float hv = (vv[j] - mu) * rs * lng[c] + lnb[c];
            As[r][c] = fmaxf(hv, 0.0f);
        }
    }
    __syncthreads();

    float acc[8][4];
#pragma unroll
    for (int i = 0; i < 8; i++)
#pragma unroll
        for (int j = 0; j < 4; j++) acc[i][j] = 0.0f;

    for (int k0 = 0; k0 < HID; k0 += 16) {
#pragma unroll
        for (int i = 0; i < 8; i++) {
            int idx = t + i * 256;
            int r = idx >> 7, c = idx & 127;
            Bs[r][c] = W[(k0 + r) * HID + c];
        }
        __syncthreads();
#pragma unroll
        for (int k = 0; k < 16; k++) {
            float a[8];
#pragma unroll
            for (int i = 0; i < 8; i++) a[i] = As[ty * 8 + i][k0 + k];
            float4 bv = *(const float4*)&Bs[k][tx * 4];
#pragma unroll
            for (int i = 0; i < 8; i++) {
                acc[i][0] += a[i] * bv.x;
                acc[i][1] += a[i] * bv.y;
                acc[i][2] += a[i] * bv.z;
                acc[i][3] += a[i] * bv.w;
            }
        }
        __syncthreads();
    }

#pragma unroll
    for (int i = 0; i < 8; i++) {
        int row = row0 + ty * 8 + i;
        if (row < NN) {
#pragma unroll
            for (int j = 0; j < 4; j++)
                g_h[row * HID + tx * 4 + j] = acc[i][j] + bb[tx * 4 + j];
        }
    }
}

// ---------------- pass 1: Xe[e] = (sum_{v in e} h[v]) * inv_ce[e] ----------
// one warp per edge; CSR gather, register accumulation, no atomics
__global__ void gather_ve_kernel() {
    int w = (blockIdx.x * blockDim.x + threadIdx.x) >> 5;
    int lane = threadIdx.x & 31;
    if (w >= MM) return;
    int beg = g_off_e[w], end = g_off_e[w + 1];

    float4 acc = make_float4(0.f, 0.f, 0.f, 0.f);
    int j = beg;
    for (; j + 32 <= end; j += 32) {
        int vi = g_csr_ev[j + lane];
#pragma unroll
        for (int k = 0; k < 32; k += 4) {
            int v0 = __shfl_sync(0xffffffffu, vi, k);
            int v1 = __shfl_sync(0xffffffffu, vi, k + 1);
            int v2 = __shfl_sync(0xffffffffu, vi, k + 2);
            int v3 = __shfl_sync(0xffffffffu, vi, k + 3);
            float4 a0 = *(const float4*)&g_h[v0 * HID + lane * 4];
            float4 a1 = *(const float4*)&g_h[v1 * HID + lane * 4];
            float4 a2 = *(const float4*)&g_h[v2 * HID + lane * 4];
            float4 a3 = *(const float4*)&g_h[v3 * HID + lane * 4];
            acc.x += a0.x + a1.x + a2.x + a3.x;
            acc.y += a0.y + a1.y + a2.y + a3.y;
            acc.z += a0.z + a1.z + a2.z + a3.z;
            acc.w += a0.w + a1.w + a2.w + a3.w;
        }
    }
    int rem = end - j;
    if (rem > 0) {
        int vi = (lane < rem) ? g_csr_ev[j + lane] : 0;
        for (int k = 0; k < rem; k++) {
            int v = __shfl_sync(0xffffffffu, vi, k);
            float4 a = *(const float4*)&g_h[v * HID + lane * 4];
            acc.x += a.x; acc.y += a.y; acc.z += a.z; acc.w += a.w;
        }
    }
    float sc = g_inv_ce[w];
    acc.x *= sc; acc.y *= sc; acc.z *= sc; acc.w *= sc;
    *(float4*)&g_xe[w * HID + lane * 4] = acc;
}

// ---------------- pass 2 (fused update): x[v] += relu(mean_e Xe[e]) --------
// one warp per vertex
__global__ void gather_ev_kernel() {
    int w = (blockIdx.x * blockDim.x + threadIdx.x) >> 5;
    int lane = threadIdx.x & 31;
    if (w >= NN) return;
    int beg = g_off_v[w], end = g_off_v[w + 1];

    float4 acc = make_float4(0.f, 0.f, 0.f, 0.f);
    int j = beg;
    for (; j + 32 <= end; j += 32) {
        int ei = g_csr_ve[j + lane];
#pragma unroll
        for (int k = 0; k < 32; k += 4) {
            int e0 = __shfl_sync(0xffffffffu, ei, k);
            int e1 = __shfl_sync(0xffffffffu, ei, k + 1);
            int e2 = __shfl_sync(0xffffffffu, ei, k + 2);
            int e3 = __shfl_sync(0xffffffffu, ei, k + 3);
            float4 a0 = *(const float4*)&g_xe[e0 * HID + lane * 4];
            float4 a1 = *(const float4*)&g_xe[e1 * HID + lane * 4];
            float4 a2 = *(const float4*)&g_xe[e2 * HID + lane * 4];
            float4 a3 = *(const float4*)&g_xe[e3 * HID + lane * 4];
            acc.x += a0.x + a1.x + a2.x + a3.x;
            acc.y += a0.y + a1.y + a2.y + a3.y;
            acc.z += a0.z + a1.z + a2.z + a3.z;
            acc.w += a0.w + a1.w + a2.w + a3.w;
        }
    }
    int rem = end - j;
    if (rem > 0) {
        int ei = (lane < rem) ? g_csr_ve[j + lane] : 0;
        for (int k = 0; k < rem; k++) {
            int e = __shfl_sync(0xffffffffu, ei, k);
            float4 a = *(const float4*)&g_xe[e * HID + lane * 4];
            acc.x += a.x; acc.y += a.y; acc.z += a.z; acc.w += a.w;
        }
    }
    float s = g_inv_cv[w];
    float4 x = *(const float4*)&g_x[w * HID + lane * 4];
    x.x += fmaxf(acc.x * s, 0.0f);
    x.y += fmaxf(acc.y * s, 0.0f);
    x.z += fmaxf(acc.z * s, 0.0f);
    x.w += fmaxf(acc.w * s, 0.0f);
    *(float4*)&g_x[w * HID + lane * 4] = x;
}

// ---------------- head: log_softmax(x @ W_out + b_out) ---------------------
__global__ void out_kernel(const float* __restrict__ Wo,
                           const float* __restrict__ bo,
                           float* __restrict__ out) {
    __shared__ float WsT[NOUT][HID];
    __shared__ float bs[NOUT];
    int t = threadIdx.x;
    for (int i = t; i < HID * NOUT; i += 256) {
        int k = i >> 4, o = i & 15;
        WsT[o][k] = Wo[i];
    }
    if (t < NOUT) bs[t] = bo[t];
    __syncthreads();

    int w = (blockIdx.x * 256 + t) >> 5;
    int lane = t & 31;
    if (w >= NN) return;
    float4 x = *(const float4*)&g_x[w * HID + lane * 4];

    float r[NOUT];
#pragma unroll
    for (int o = 0; o < NOUT; o++) {
        float4 wv = *(const float4*)&WsT[o][lane * 4];
        float p = x.x * wv.x + x.y * wv.y + x.z * wv.z + x.w * wv.w;
#pragma unroll
        for (int off = 16; off > 0; off >>= 1)
            p += __shfl_xor_sync(0xffffffffu, p, off);
        r[o] = p + bs[o];
    }

    float m = r[0];
#pragma unroll
    for (int o = 1; o < NOUT; o++) m = fmaxf(m, r[o]);
    float sum = 0.0f;
#pragma unroll
    for (int o = 0; o < NOUT; o++) sum += expf(r[o] - m);
    float lse = m + logf(sum);

    if (lane == 0) {
#pragma unroll
        for (int o = 0; o < NOUT; o++)
            out[w * NOUT + o] = r[o] - lse;
    }
}

// ---------------- launcher ----------------
extern "C" void kernel_launch(void* const* d_in, const int* in_sizes, int n_in,
                              void* d_out, int out_size) {
    const float* X     = (const float*)d_in[0];
    const int*   v_idx = (const int*)  d_in[1];
    const int*   e_idx = (const int*)  d_in[2];
    const float* W_enc = (const float*)d_in[3];
    const float* b_enc = (const float*)d_in[4];
    const float* ln_g  = (const float*)d_in[5];
    const float* ln_b  = (const float*)d_in[6];
    const float* Wt    = (const float*)d_in[7];
    const float* bt    = (const float*)d_in[8];
    const float* W_out = (const float*)d_in[9];
    const float* b_out = (const float*)d_in[10];
    float* out = (float*)d_out;

    // degrees + CSR build (amortized over 16 layers)
    zero_counts_kernel<<<(NN + 255) / 256, 256>>>();
    count_kernel<<<(PP + 255) / 256, 256>>>(v_idx, e_idx);
    inv_kernel<<<(NN + 255) / 256, 256>>>();
    int* off_e; cudaGetSymbolAddress((void**)&off_e, g_off_e);
    int* off_v; cudaGetSymbolAddress((void**)&off_v, g_off_v);
    int* cnt_e; cudaGetSymbolAddress((void**)&cnt_e, g_cnt_e);
    int* cnt_v; cudaGetSymbolAddress((void**)&cnt_v, g_cnt_v);
    int* cur_e; cudaGetSymbolAddress((void**)&cur_e, g_cur_e);
    int* cur_v; cudaGetSymbolAddress((void**)&cur_v, g_cur_v);
    scan_kernel<<<1, 1024>>>(cnt_e, off_e, cur_e, MM);
    scan_kernel<<<1, 1024>>>(cnt_v, off_v, cur_v, NN);
    fill_csr_kernel<<<(PP + 255) / 256, 256>>>(v_idx, e_idx);

    // encoder
    enc_gemm_kernel<<<(NN + 63) / 64, 256>>>(X, W_enc, b_enc);

    for (int l = 0; l < NLAYERS; l++) {
        ln_gemm_kernel<<<(NN + 63) / 64, 256>>>(ln_g + l * HID, ln_b + l * HID,
                                                Wt + l * HID * HID, bt + l * HID);
        gather_ve_kernel<<<(MM + 7) / 8, 256>>>();
        gather_ev_kernel<<<(NN + 7) / 8, 256>>>();
    }

    out_kernel<<<NN / 8, 256>>>(W_out, b_out, out);
}

// round 3
// speedup vs baseline: 2.3800x; 1.1918x over previous
#include <cuda_runtime.h>
#include <cuda_fp16.h>

#define NN 100000
#define MM 20000
#define PP 1600000
#define CIN 768
#define HID 128
#define NLAYERS 16
#define NOUT 16
#define EPSV 1e-5f

// ---------------- scratch (device globals; no dynamic allocation) ----------
__device__ float  g_x[NN * HID];      // node features (residual stream, fp32)
__device__ __half g_h[NN * HID];      // post-theta features (fp16 payload)
__device__ __half g_xe[MM * HID];     // per-edge features (fp16 payload)
__device__ float  g_inv_ce[MM];
__device__ float  g_inv_cv[NN];
__device__ int    g_cnt_e[MM];
__device__ int    g_cnt_v[NN];
__device__ int    g_off_e[MM + 1];
__device__ int    g_off_v[NN + 1];
__device__ int    g_cur_e[MM];
__device__ int    g_cur_v[NN];
__device__ int    g_csr_ev[PP];       // vertex ids grouped by edge
__device__ int    g_csr_ve[PP];       // edge ids grouped by vertex

// ---------------- degree counting ----------------
__global__ void zero_counts_kernel() {
    int i = blockIdx.x * blockDim.x + threadIdx.x;
    if (i < MM) g_cnt_e[i] = 0;
    if (i < NN) g_cnt_v[i] = 0;
}

__global__ void count_kernel(const int* __restrict__ v_idx,
                             const int* __restrict__ e_idx) {
    int i = blockIdx.x * blockDim.x + threadIdx.x;
    if (i < PP) {
        atomicAdd(&g_cnt_e[e_idx[i]], 1);
        atomicAdd(&g_cnt_v[v_idx[i]], 1);
    }
}

__global__ void inv_kernel() {
    int i = blockIdx.x * blockDim.x + threadIdx.x;
    if (i < MM) g_inv_ce[i] = 1.0f / fmaxf((float)g_cnt_e[i], 1.0f);
    if (i < NN) g_inv_cv[i] = 1.0f / fmaxf((float)g_cnt_v[i], 1.0f);
}

// ---------------- single-block exclusive scan ------------------------------
__global__ void scan_kernel(const int* __restrict__ cnt, int* __restrict__ off,
                            int* __restrict__ cur, int n) {
    __shared__ int warp_sums[32];
    __shared__ int s_carry;
    int t = threadIdx.x;
    int lane = t & 31, wid = t >> 5;
    if (t == 0) { s_carry = 0; off[0] = 0; }
    __syncthreads();
    for (int base = 0; base < n; base += 1024) {
        int i = base + t;
        int v = (i < n) ? cnt[i] : 0;
        if (i < n) cur[i] = 0;
        int x = v;
#pragma unroll
        for (int d = 1; d < 32; d <<= 1) {
            int y = __shfl_up_sync(0xffffffffu, x, d);
            if (lane >= d) x += y;
        }
        if (lane == 31) warp_sums[wid] = x;
        __syncthreads();
        if (wid == 0) {
            int ws = warp_sums[lane];
#pragma unroll
            for (int d = 1; d < 32; d <<= 1) {
                int y = __shfl_up_sync(0xffffffffu, ws, d);
                if (lane >= d) ws += y;
            }
            warp_sums[lane] = ws;
        }
        __syncthreads();
        int incl = x + (wid > 0 ? warp_sums[wid - 1] : 0) + s_carry;
        if (i < n) off[i + 1] = incl;
        __syncthreads();
        if (t == 1023) s_carry = incl;
        __syncthreads();
    }
}

// ---------------- CSR fill --------------------------------------------------
__global__ void fill_csr_kernel(const int* __restrict__ v_idx,
                                const int* __restrict__ e_idx) {
    int i = blockIdx.x * blockDim.x + threadIdx.x;
    if (i >= PP) return;
    int v = v_idx[i];
    int e = e_idx[i];
    int pe = atomicAdd(&g_cur_e[e], 1);
    g_csr_ev[g_off_e[e] + pe] = v;
    int pv = atomicAdd(&g_cur_v[v], 1);
    g_csr_ve[g_off_v[v] + pv] = e;
}

// ---------------- encoder GEMM: g_x = X @ W_enc + b_enc --------------------
__global__ void enc_gemm_kernel(const float* __restrict__ X,
                                const float* __restrict__ W,
                                const float* __restrict__ bias) {
    __shared__ float As[64][20];
    __shared__ float Bs[16][128];
    int t = threadIdx.x;
    int ty = t >> 5;
    int tx = t & 31;
    int row0 = blockIdx.x * 64;

    float acc[8][4];
#pragma unroll
    for (int i = 0; i < 8; i++)
#pragma unroll
        for (int j = 0; j < 4; j++) acc[i][j] = 0.0f;

    for (int k0 = 0; k0 < CIN; k0 += 16) {
#pragma unroll
        for (int i = 0; i < 4; i++) {
            int idx = t + i * 256;
            int r = idx >> 4, c = idx & 15;
            int row = row0 + r;
            As[r][c] = (row < NN) ? X[row * CIN + k0 + c] : 0.0f;
        }
#pragma unroll
        for (int i = 0; i < 8; i++) {
            int idx = t + i * 256;
            int r = idx >> 7, c = idx & 127;
            Bs[r][c] = W[(k0 + r) * HID + c];
        }
        __syncthreads();
#pragma unroll
        for (int k = 0; k < 16; k++) {
            float a[8];
#pragma unroll
            for (int i = 0; i < 8; i++) a[i] = As[ty * 8 + i][k];
            float4 bv = *(const float4*)&Bs[k][tx * 4];
#pragma unroll
            for (int i = 0; i < 8; i++) {
                acc[i][0] += a[i] * bv.x;
                acc[i][1] += a[i] * bv.y;
                acc[i][2] += a[i] * bv.z;
                acc[i][3] += a[i] * bv.w;
            }
        }
        __syncthreads();
    }

#pragma unroll
    for (int i = 0; i < 8; i++) {
        int row = row0 + ty * 8 + i;
        if (row < NN) {
#pragma unroll
            for (int j = 0; j < 4; j++)
                g_x[row * HID + tx * 4 + j] = acc[i][j] + bias[tx * 4 + j];
        }
    }
}

// ---------------- per-layer: h = relu(LN(x)*g+b) @ W + bb  (h -> fp16) -----
__global__ void ln_gemm_kernel(const float* __restrict__ lng,
                               const float* __restrict__ lnb,
                               const float* __restrict__ W,
                               const float* __restrict__ bb) {
    __shared__ float As[64][132];
    __shared__ float Bs[16][128];
    int t = threadIdx.x;
    int ty = t >> 5;
    int tx = t & 31;
    int row0 = blockIdx.x * 64;

#pragma unroll
    for (int rr = 0; rr < 8; rr++) {
        int r = ty * 8 + rr;
        int row = row0 + r;
        float4 v = make_float4(0.f, 0.f, 0.f, 0.f);
        if (row < NN) v = *(const float4*)&g_x[row * HID + tx * 4];
        float s  = v.x + v.y + v.z + v.w;
        float sq = v.x * v.x + v.y * v.y + v.z * v.z + v.w * v.w;
#pragma unroll
        for (int off = 16; off > 0; off >>= 1) {
            s  += __shfl_xor_sync(0xffffffffu, s, off);
            sq += __shfl_xor_sync(0xffffffffu, sq, off);
        }
        float mu  = s * (1.0f / 128.0f);
        float var = sq * (1.0f / 128.0f) - mu * mu;
        float rs  = rsqrtf(var + EPSV);
        float vv[4] = {v.x, v.y, v.z, v.w};
#pragma unroll
        for (int j = 0; j < 4; j++) {
            int c = tx * 4 + j;
            float hv = (vv[j] - mu) * rs * lng[c] + lnb[c];
            As[r][c] = fmaxf(hv, 0.0f);
        }
    }
    __syncthreads();

    float acc[8][4];
#pragma unroll
    for (int i = 0; i < 8; i++)
#pragma unroll
        for (int j = 0; j < 4; j++) acc[i][j] = 0.0f;

    for (int k0 = 0; k0 < HID; k0 += 16) {
#pragma unroll
        for (int i = 0; i < 8; i++) {
            int idx = t + i * 256;
            int r = idx >> 7, c = idx & 127;
            Bs[r][c] = W[(k0 + r) * HID + c];
        }
        __syncthreads();
#pragma unroll
        for (int k = 0; k < 16; k++) {
            float a[8];
#pragma unroll
            for (int i = 0; i < 8; i++) a[i] = As[ty * 8 + i][k0 + k];
            float4 bv = *(const float4*)&Bs[k][tx * 4];
#pragma unroll
            for (int i = 0; i < 8; i++) {
                acc[i][0] += a[i] * bv.x;
                acc[i][1] += a[i] * bv.y;
                acc[i][2] += a[i] * bv.z;
                acc[i][3] += a[i] * bv.w;
            }
        }
        __syncthreads();
    }

#pragma unroll
    for (int i = 0; i < 8; i++) {
        int row = row0 + ty * 8 + i;
        if (row < NN) {
            float b0 = bb[tx * 4 + 0], b1 = bb[tx * 4 + 1];
            float b2 = bb[tx * 4 + 2], b3 = bb[tx * 4 + 3];
            __half2 h01 = __floats2half2_rn(acc[i][0] + b0, acc[i][1] + b1);
            __half2 h23 = __floats2half2_rn(acc[i][2] + b2, acc[i][3] + b3);
            uint2 u;
            u.x = *(unsigned*)&h01;
            u.y = *(unsigned*)&h23;
            *(uint2*)&g_h[row * HID + tx * 4] = u;
        }
    }
}

// helper: load 4 halves (8B) and add into float4 accumulator
__device__ __forceinline__ void acc_half4(float4& acc, const __half* p) {
    uint2 u = *(const uint2*)p;
    __half2 a = *(__half2*)&u.x;
    __half2 b = *(__half2*)&u.y;
    float2 fa = __half22float2(a);
    float2 fb = __half22float2(b);
    acc.x += fa.x; acc.y += fa.y; acc.z += fb.x; acc.w += fb.y;
}

// ---------------- pass 1: Xe[e] = (sum_{v in e} h[v]) * inv_ce[e] ----------
__global__ void gather_ve_kernel() {
    int w = (blockIdx.x * blockDim.x + threadIdx.x) >> 5;
    int lane = threadIdx.x & 31;
    if (w >= MM) return;
    int beg = g_off_e[w], end = g_off_e[w + 1];

    float4 acc = make_float4(0.f, 0.f, 0.f, 0.f);
    int j = beg;
    for (; j + 32 <= end; j += 32) {
        int vi = g_csr_ev[j + lane];
#pragma unroll
        for (int k = 0; k < 32; k += 4) {
            int v0 = __shfl_sync(0xffffffffu, vi, k);
            int v1 = __shfl_sync(0xffffffffu, vi, k + 1);
            int v2 = __shfl_sync(0xffffffffu, vi, k + 2);
            int v3 = __shfl_sync(0xffffffffu, vi, k + 3);
            acc_half4(acc, &g_h[v0 * HID + lane * 4]);
            acc_half4(acc, &g_h[v1 * HID + lane * 4]);
            acc_half4(acc, &g_h[v2 * HID + lane * 4]);
            acc_half4(acc, &g_h[v3 * HID + lane * 4]);
        }
    }
    int rem = end - j;
    if (rem > 0) {
        int vi = (lane < rem) ? g_csr_ev[j + lane] : 0;
        for (int k = 0; k < rem; k++) {
            int v = __shfl_sync(0xffffffffu, vi, k);
            acc_half4(acc, &g_h[v * HID + lane * 4]);
        }
    }
    float sc = g_inv_ce[w];
    __half2 h01 = __floats2half2_rn(acc.x * sc, acc.y * sc);
    __half2 h23 = __floats2half2_rn(acc.z * sc, acc.w * sc);
    uint2 u;
    u.x = *(unsigned*)&h01;
    u.y = *(unsigned*)&h23;
    *(uint2*)&g_xe[w * HID + lane * 4] = u;
}

// ---------------- pass 2 (fused update): x[v] += relu(mean_e Xe[e]) --------
__global__ void gather_ev_kernel() {
    int w = (blockIdx.x * blockDim.x + threadIdx.x) >> 5;
    int lane = threadIdx.x & 31;
    if (w >= NN) return;
    int beg = g_off_v[w], end = g_off_v[w + 1];

    float4 acc = make_float4(0.f, 0.f, 0.f, 0.f);
    int j = beg;
    for (; j + 32 <= end; j += 32) {
        int ei = g_csr_ve[j + lane];
#pragma unroll
        for (int k = 0; k < 32; k += 4) {
            int e0 = __shfl_sync(0xffffffffu, ei, k);
            int e1 = __shfl_sync(0xffffffffu, ei, k + 1);
            int e2 = __shfl_sync(0xffffffffu, ei, k + 2);
            int e3 = __shfl_sync(0xffffffffu, ei, k + 3);
            acc_half4(acc, &g_xe[e0 * HID + lane * 4]);
            acc_half4(acc, &g_xe[e1 * HID + lane * 4]);
            acc_half4(acc, &g_xe[e2 * HID + lane * 4]);
            acc_half4(acc, &g_xe[e3 * HID + lane * 4]);
        }
    }
    int rem = end - j;
    if (rem > 0) {
        int ei = (lane < rem) ? g_csr_ve[j + lane] : 0;
        for (int k = 0; k < rem; k++) {
            int e = __shfl_sync(0xffffffffu, ei, k);
            acc_half4(acc, &g_xe[e * HID + lane * 4]);
        }
    }
    float s = g_inv_cv[w];
    float4 x = *(const float4*)&g_x[w * HID + lane * 4];
    x.x += fmaxf(acc.x * s, 0.0f);
    x.y += fmaxf(acc.y * s, 0.0f);
    x.z += fmaxf(acc.z * s, 0.0f);
    x.w += fmaxf(acc.w * s, 0.0f);
    *(float4*)&g_x[w * HID + lane * 4] = x;
}

// ---------------- head: log_softmax(x @ W_out + b_out) ---------------------
__global__ void out_kernel(const float* __restrict__ Wo,
                           const float* __restrict__ bo,
                           float* __restrict__ out) {
    __shared__ float WsT[NOUT][HID];
    __shared__ float bs[NOUT];
    int t = threadIdx.x;
    for (int i = t; i < HID * NOUT; i += 256) {
        int k = i >> 4, o = i & 15;
        WsT[o][k] = Wo[i];
    }
    if (t < NOUT) bs[t] = bo[t];
    __syncthreads();

    int w = (blockIdx.x * 256 + t) >> 5;
    int lane = t & 31;
    if (w >= NN) return;
    float4 x = *(const float4*)&g_x[w * HID + lane * 4];

    float r[NOUT];
#pragma unroll
    for (int o = 0; o < NOUT; o++) {
        float4 wv = *(const float4*)&WsT[o][lane * 4];
        float p = x.x * wv.x + x.y * wv.y + x.z * wv.z + x.w * wv.w;
#pragma unroll
        for (int off = 16; off > 0; off >>= 1)
            p += __shfl_xor_sync(0xffffffffu, p, off);
        r[o] = p + bs[o];
    }

    float m = r[0];
#pragma unroll
    for (int o = 1; o < NOUT; o++) m = fmaxf(m, r[o]);
    float sum = 0.0f;
#pragma unroll
    for (int o = 0; o < NOUT; o++) sum += expf(r[o] - m);
    float lse = m + logf(sum);

    if (lane == 0) {
#pragma unroll
        for (int o = 0; o < NOUT; o++)
            out[w * NOUT + o] = r[o] - lse;
    }
}

// ---------------- launcher ----------------
extern "C" void kernel_launch(void* const* d_in, const int* in_sizes, int n_in,
                              void* d_out, int out_size) {
    const float* X     = (const float*)d_in[0];
    const int*   v_idx = (const int*)  d_in[1];
    const int*   e_idx = (const int*)  d_in[2];
    const float* W_enc = (const float*)d_in[3];
    const float* b_enc = (const float*)d_in[4];
    const float* ln_g  = (const float*)d_in[5];
    const float* ln_b  = (const float*)d_in[6];
    const float* Wt    = (const float*)d_in[7];
    const float* bt    = (const float*)d_in[8];
    const float* W_out = (const float*)d_in[9];
    const float* b_out = (const float*)d_in[10];
    float* out = (float*)d_out;

    zero_counts_kernel<<<(NN + 255) / 256, 256>>>();
    count_kernel<<<(PP + 255) / 256, 256>>>(v_idx, e_idx);
    inv_kernel<<<(NN + 255) / 256, 256>>>();
    int* off_e; cudaGetSymbolAddress((void**)&off_e, g_off_e);
    int* off_v; cudaGetSymbolAddress((void**)&off_v, g_off_v);
    int* cnt_e; cudaGetSymbolAddress((void**)&cnt_e, g_cnt_e);
    int* cnt_v; cudaGetSymbolAddress((void**)&cnt_v, g_cnt_v);
    int* cur_e; cudaGetSymbolAddress((void**)&cur_e, g_cur_e);
    int* cur_v; cudaGetSymbolAddress((void**)&cur_v, g_cur_v);
    scan_kernel<<<1, 1024>>>(cnt_e, off_e, cur_e, MM);
    scan_kernel<<<1, 1024>>>(cnt_v, off_v, cur_v, NN);
    fill_csr_kernel<<<(PP + 255) / 256, 256>>>(v_idx, e_idx);

    enc_gemm_kernel<<<(NN + 63) / 64, 256>>>(X, W_enc, b_enc);

    for (int l = 0; l < NLAYERS; l++) {
        ln_gemm_kernel<<<(NN + 63) / 64, 256>>>(ln_g + l * HID, ln_b + l * HID,
                                                Wt + l * HID * HID, bt + l * HID);
        gather_ve_kernel<<<(MM + 7) / 8, 256>>>();
        gather_ev_kernel<<<(NN + 7) / 8, 256>>>();
    }

    out_kernel<<<NN / 8, 256>>>(W_out, b_out, out);
}

// round 5
// speedup vs baseline: 3.8554x; 1.6199x over previous
#include <cuda_runtime.h>
#include <cuda_fp16.h>
#include <stdint.h>

#define NN 100000
#define MM 20000
#define PP 1600000
#define CIN 768
#define HID 128
#define NLAYERS 16
#define NOUT 16
#define EPSV 1e-5f

// ---------------- scratch ----------------
__device__ float  g_x[NN * HID];        // residual stream fp32
__device__ __half g_h[NN * HID];        // post-theta fp16
__device__ __half g_xe[MM * HID];       // edge features fp16
__device__ __half g_xh[NN * CIN];       // X in fp16
__device__ __half g_weT[HID * CIN];     // W_enc^T  [n][k]
__device__ __half g_wtT[NLAYERS * HID * HID]; // Wt^T per layer [n][k]
__device__ float  g_inv_ce[MM];
__device__ float  g_inv_cv[NN];
__device__ int    g_cnt_e[MM];
__device__ int    g_cnt_v[NN];
__device__ int    g_off_e[MM + 1];
__device__ int    g_off_v[NN + 1];
__device__ int    g_cur_e[MM];
__device__ int    g_cur_v[NN];
__device__ int    g_csr_ev[PP];
__device__ int    g_csr_ve[PP];

// ---------------- degree counting ----------------
__global__ void zero_counts_kernel() {
    int i = blockIdx.x * blockDim.x + threadIdx.x;
    if (i < MM) g_cnt_e[i] = 0;
    if (i < NN) g_cnt_v[i] = 0;
}

__global__ void count_kernel(const int* __restrict__ v_idx,
                             const int* __restrict__ e_idx) {
    int i = blockIdx.x * blockDim.x + threadIdx.x;
    if (i < PP) {
        atomicAdd(&g_cnt_e[e_idx[i]], 1);
        atomicAdd(&g_cnt_v[v_idx[i]], 1);
    }
}

__global__ void inv_kernel() {
    int i = blockIdx.x * blockDim.x + threadIdx.x;
    if (i < MM) g_inv_ce[i] = 1.0f / fmaxf((float)g_cnt_e[i], 1.0f);
    if (i < NN) g_inv_cv[i] = 1.0f / fmaxf((float)g_cnt_v[i], 1.0f);
}

// ---------------- single-block exclusive scan ------------------------------
__global__ void scan_kernel(const int* __restrict__ cnt, int* __restrict__ off,
                            int* __restrict__ cur, int n) {
    __shared__ int warp_sums[32];
    __shared__ int s_carry;
    int t = threadIdx.x;
    int lane = t & 31, wid = t >> 5;
    if (t == 0) { s_carry = 0; off[0] = 0; }
    __syncthreads();
    for (int base = 0; base < n; base += 1024) {
        int i = base + t;
        int v = (i < n) ? cnt[i] : 0;
        if (i < n) cur[i] = 0;
        int x = v;
#pragma unroll
        for (int d = 1; d < 32; d <<= 1) {
            int y = __shfl_up_sync(0xffffffffu, x, d);
            if (lane >= d) x += y;
        }
        if (lane == 31) warp_sums[wid] = x;
        __syncthreads();
        if (wid == 0) {
            int ws = warp_sums[lane];
#pragma unroll
            for (int d = 1; d < 32; d <<= 1) {
                int y = __shfl_up_sync(0xffffffffu, ws, d);
                if (lane >= d) ws += y;
            }
            warp_sums[lane] = ws;
        }
        __syncthreads();
        int incl = x + (wid > 0 ? warp_sums[wid - 1] : 0) + s_carry;
        if (i < n) off[i + 1] = incl;
        __syncthreads();
        if (t == 1023) s_carry = incl;
        __syncthreads();
    }
}

// ---------------- CSR fill --------------------------------------------------
__global__ void fill_csr_kernel(const int* __restrict__ v_idx,
                                const int* __restrict__ e_idx) {
    int i = blockIdx.x * blockDim.x + threadIdx.x;
    if (i >= PP) return;
    int v = v_idx[i];
    int e = e_idx[i];
    int pe = atomicAdd(&g_cur_e[e], 1);
    g_csr_ev[g_off_e[e] + pe] = v;
    int pv = atomicAdd(&g_cur_v[v], 1);
    g_csr_ve[g_off_v[v] + pv] = e;
}

// ---------------- conversions ----------------
__global__ void convert_x_kernel(const float* __restrict__ X) {
    int i = blockIdx.x * blockDim.x + threadIdx.x;   // float4 granularity
    if (i >= NN * CIN / 4) return;
    float4 v = ((const float4*)X)[i];
    __half2 h01 = __floats2half2_rn(v.x, v.y);
    __half2 h23 = __floats2half2_rn(v.z, v.w);
    uint2 u;
    u.x = *(unsigned*)&h01;
    u.y = *(unsigned*)&h23;
    *(uint2*)&g_xh[i * 4] = u;
}

__global__ void convert_w_kernel(const float* __restrict__ We,
                                 const float* __restrict__ Wt) {
    int i = blockIdx.x * blockDim.x + threadIdx.x;
    if (i < CIN * HID) {                 // We[k][n] -> g_weT[n][k]
        int k = i / HID, n = i % HID;
        g_weT[n * CIN + k] = __float2half(We[i]);
    }
    if (i < NLAYERS * HID * HID) {       // Wt[l][k][n] -> g_wtT[l][n][k]
        int l = i >> 14;
        int r = i & 16383;
        int k = r >> 7, n = r & 127;
        g_wtT[(l << 14) + n * HID + k] = __float2half(Wt[i]);
    }
}

// ---------------- mma helper ----------------
__device__ __forceinline__ void mma16816(float* c, uint32_t a0, uint32_t a1,
                                         uint32_t a2, uint32_t a3,
                                         uint32_t b0, uint32_t b1) {
    asm volatile(
        "mma.sync.aligned.m16n8k16.row.col.f32.f16.f16.f32 "
        "{%0,%1,%2,%3},{%4,%5,%6,%7},{%8,%9},{%0,%1,%2,%3};"
        : "+f"(c[0]), "+f"(c[1]), "+f"(c[2]), "+f"(c[3])
        : "r"(a0), "r"(a1), "r"(a2), "r"(a3), "r"(b0), "r"(b1));
}

// ---------------- encoder GEMM (tensor core): g_x = X@W_enc + b ------------
// block: 64 rows x 128 cols, 8 warps (4 m x 2 n), K streamed 16 at a time.
__global__ void enc_mma_kernel(const float* __restrict__ bias) {
    __shared__ __half As[2][64][24];     // 16 + 8 pad
    __shared__ __half Bs[2][128][24];
    int t = threadIdx.x;
    int lane = t & 31, wid = t >> 5;
    int wr = wid >> 1, wc = wid & 1;
    int row0 = blockIdx.x * 64;

    float acc[8][4];
#pragma unroll
    for (int j = 0; j < 8; j++)
#pragma unroll
        for (int q = 0; q < 4; q++) acc[j][q] = 0.0f;

    // prefetch chunk 0
    {
        int kk = (t & 1) * 8;
        if (t < 128) {
            int row = t >> 1;
            int gr = row0 + row;
            uint4 u = make_uint4(0, 0, 0, 0);
            if (gr < NN) u = *(const uint4*)&g_xh[gr * CIN + kk];
            *(uint4*)&As[0][row][kk] = u;
        }
        int n = t >> 1;
        *(uint4*)&Bs[0][n][kk] = *(const uint4*)&g_weT[n * CIN + kk];
    }
    __syncthreads();

    for (int c = 0; c < CIN / 16; c++) {
        int cur = c & 1, nxt = cur ^ 1;
        if (c + 1 < CIN / 16) {
            int k0 = (c + 1) * 16;
            int kk = (t & 1) * 8;
            if (t < 128) {
                int row = t >> 1;
                int gr = row0 + row;
                uint4 u = make_uint4(0, 0, 0, 0);
                if (gr < NN) u = *(const uint4*)&g_xh[gr * CIN + k0 + kk];
                *(uint4*)&As[nxt][row][kk] = u;
            }
            int n = t >> 1;
            *(uint4*)&Bs[nxt][n][kk] = *(const uint4*)&g_weT[n * CIN + k0 + kk];
        }
        int ar = wr * 16 + (lane >> 2);
        int cx = (lane & 3) * 2;
        uint32_t a0 = *(uint32_t*)&As[cur][ar][cx];
        uint32_t a1 = *(uint32_t*)&As[cur][ar + 8][cx];
        uint32_t a2 = *(uint32_t*)&As[cur][ar][cx + 8];
        uint32_t a3 = *(uint32_t*)&As[cur][ar + 8][cx + 8];
#pragma unroll
        for (int j = 0; j < 8; j++) {
            int n = wc * 64 + j * 8 + (lane >> 2);
            uint32_t b0 = *(uint32_t*)&Bs[cur][n][cx];
            uint32_t b1 = *(uint32_t*)&Bs[cur][n][cx + 8];
            mma16816(acc[j], a0, a1, a2, a3, b0, b1);
        }
        __syncthreads();
    }

    int r1 = row0 + wr * 16 + (lane >> 2);
    int r2 = r1 + 8;
#pragma unroll
    for (int j = 0; j < 8; j++) {
        int cb = wc * 64 + j * 8 + (lane & 3) * 2;
        float b0 = bias[cb], b1 = bias[cb + 1];
        if (r1 < NN)
            *(float2*)&g_x[r1 * HID + cb] = make_float2(acc[j][0] + b0, acc[j][1] + b1);
        if (r2 < NN)
            *(float2*)&g_x[r2 * HID + cb] = make_float2(acc[j][2] + b0, acc[j][3] + b1);
    }
}

// ---------------- per-layer (tensor core): h = relu(LN(x)) @ W + bb --------
// block: 64 rows x 128 cols; W loaded in 2 K-stages of 64.
__global__ void ln_mma_kernel(const float* __restrict__ lng,
                              const float* __restrict__ lnb,
                              const __half* __restrict__ WtT,   // [n][k]
                              const float* __restrict__ bb) {
    __shared__ __half As[64][136];       // 128 + 8 pad
    __shared__ __half Ws[128][72];       // 64 + 8 pad
    int t = threadIdx.x;
    int lane = t & 31, wid = t >> 5;
    int wr = wid >> 1, wc = wid & 1;
    int row0 = blockIdx.x * 64;

    // LN phase: warp wid handles rows wid*8 .. wid*8+7
    float4 lg = *(const float4*)&lng[lane * 4];
    float4 lb = *(const float4*)&lnb[lane * 4];
#pragma unroll
    for (int rr = 0; rr < 8; rr++) {
        int r = wid * 8 + rr;
        int row = row0 + r;
        float4 v = make_float4(0.f, 0.f, 0.f, 0.f);
        if (row < NN) v = *(const float4*)&g_x[row * HID + lane * 4];
        float s  = v.x + v.y + v.z + v.w;
        float sq = v.x * v.x + v.y * v.y + v.z * v.z + v.w * v.w;
#pragma unroll
        for (int off = 16; off > 0; off >>= 1) {
            s  += __shfl_xor_sync(0xffffffffu, s, off);
            sq += __shfl_xor_sync(0xffffffffu, sq, off);
        }
        float mu  = s * (1.0f / 128.0f);
        float var = sq * (1.0f / 128.0f) - mu * mu;
        float rs  = rsqrtf(var + EPSV);
        float h0 = fmaxf((v.x - mu) * rs * lg.x + lb.x, 0.0f);
        float h1 = fmaxf((v.y - mu) * rs * lg.y + lb.y, 0.0f);
        float h2 = fmaxf((v.z - mu) * rs * lg.z + lb.z, 0.0f);
        float h3 = fmaxf((v.w - mu) * rs * lg.w + lb.w, 0.0f);
        __half2 p01 = __floats2half2_rn(h0, h1);
        __half2 p23 = __floats2half2_rn(h2, h3);
        uint2 u;
        u.x = *(unsigned*)&p01;
        u.y = *(unsigned*)&p23;
        *(uint2*)&As[r][lane * 4] = u;
    }
    __syncthreads();

    float acc[8][4];
#pragma unroll
    for (int j = 0; j < 8; j++)
#pragma unroll
        for (int q = 0; q < 4; q++) acc[j][q] = 0.0f;

#pragma unroll
    for (int s = 0; s < 2; s++) {
        // load W columns [s*64, s*64+64) : 128n x 64k = 1024 uint4
#pragma unroll
        for (int i = 0; i < 4; i++) {
            int idx = t + i * 256;
            int n = idx >> 3, k = (idx & 7) * 8;
            *(uint4*)&Ws[n][k] = *(const uint4*)&WtT[n * HID + s * 64 + k];
        }
        __syncthreads();
#pragma unroll
        for (int c = 0; c < 4; c++) {
            int ka = s * 64 + c * 16;   // As col
            int kw = c * 16;            // Ws col
            int ar = wr * 16 + (lane >> 2);
            int q2 = (lane & 3) * 2;
            uint32_t a0 = *(uint32_t*)&As[ar][ka + q2];
            uint32_t a1 = *(uint32_t*)&As[ar + 8][ka + q2];
            uint32_t a2 = *(uint32_t*)&As[ar][ka + q2 + 8];
            uint32_t a3 = *(uint32_t*)&As[ar + 8][ka + q2 + 8];
#pragma unroll
            for (int j = 0; j < 8; j++) {
                int n = wc * 64 + j * 8 + (lane >> 2);
                uint32_t b0 = *(uint32_t*)&Ws[n][kw + q2];
                uint32_t b1 = *(uint32_t*)&Ws[n][kw + q2 + 8];
                mma16816(acc[j], a0, a1, a2, a3, b0, b1);
            }
        }
        __syncthreads();
    }

    int r1 = row0 + wr * 16 + (lane >> 2);
    int r2 = r1 + 8;
#pragma unroll
    for (int j = 0; j < 8; j++) {
        int cb = wc * 64 + j * 8 + (lane & 3) * 2;
        float b0 = bb[cb], b1 = bb[cb + 1];
        if (r1 < NN) {
            __half2 h = __floats2half2_rn(acc[j][0] + b0, acc[j][1] + b1);
            *(unsigned*)&g_h[r1 * HID + cb] = *(unsigned*)&h;
        }
        if (r2 < NN) {
            __half2 h = __floats2half2_rn(acc[j][2] + b0, acc[j][3] + b1);
            *(unsigned*)&g_h[r2 * HID + cb] = *(unsigned*)&h;
        }
    }
}

// helper: load 4 halves (8B) and add into float4 accumulator
__device__ __forceinline__ void acc_half4(float4& acc, const __half* p) {
    uint2 u = *(const uint2*)p;
    __half2 a = *(__half2*)&u.x;
    __half2 b = *(__half2*)&u.y;
    float2 fa = __half22float2(a);
    float2 fb = __half22float2(b);
    acc.x += fa.x; acc.y += fa.y; acc.z += fb.x; acc.w += fb.y;
}

// ---------------- pass 1: Xe[e] = (sum_{v in e} h[v]) * inv_ce[e] ----------
__global__ void gather_ve_kernel() {
    int w = (blockIdx.x * blockDim.x + threadIdx.x) >> 5;
    int lane = threadIdx.x & 31;
    if (w >= MM) return;
    int beg = g_off_e[w], end = g_off_e[w + 1];

    float4 acc = make_float4(0.f, 0.f, 0.f, 0.f);
    int j = beg;
    for (; j + 32 <= end; j += 32) {
        int vi = g_csr_ev[j + lane];
#pragma unroll
        for (int k = 0; k < 32; k += 4) {
            int v0 = __shfl_sync(0xffffffffu, vi, k);
            int v1 = __shfl_sync(0xffffffffu, vi, k + 1);
            int v2 = __shfl_sync(0xffffffffu, vi, k + 2);
            int v3 = __shfl_sync(0xffffffffu, vi, k + 3);
            acc_half4(acc, &g_h[v0 * HID + lane * 4]);
            acc_half4(acc, &g_h[v1 * HID + lane * 4]);
            acc_half4(acc, &g_h[v2 * HID + lane * 4]);
            acc_half4(acc, &g_h[v3 * HID + lane * 4]);
        }
    }
    int rem = end - j;
    if (rem > 0) {
        int vi = (lane < rem) ? g_csr_ev[j + lane] : 0;
        for (int k = 0; k < rem; k++) {
            int v = __shfl_sync(0xffffffffu, vi, k);
            acc_half4(acc, &g_h[v * HID + lane * 4]);
        }
    }
    float sc = g_inv_ce[w];
    __half2 h01 = __floats2half2_rn(acc.x * sc, acc.y * sc);
    __half2 h23 = __floats2half2_rn(acc.z * sc, acc.w * sc);
    uint2 u;
    u.x = *(unsigned*)&h01;
    u.y = *(unsigned*)&h23;
    *(uint2*)&g_xe[w * HID + lane * 4] = u;
}

// ---------------- pass 2 (fused update): x[v] += relu(mean_e Xe[e]) --------
__global__ void gather_ev_kernel() {
    int w = (blockIdx.x * blockDim.x + threadIdx.x) >> 5;
    int lane = threadIdx.x & 31;
    if (w >= NN) return;
    int beg = g_off_v[w], end = g_off_v[w + 1];

    float4 acc = make_float4(0.f, 0.f, 0.f, 0.f);
    int j = beg;
    for (; j + 32 <= end; j += 32) {
        int ei = g_csr_ve[j + lane];
#pragma unroll
        for (int k = 0; k < 32; k += 4) {
            int e0 = __shfl_sync(0xffffffffu, ei, k);
            int e1 = __shfl_sync(0xffffffffu, ei, k + 1);
            int e2 = __shfl_sync(0xffffffffu, ei, k + 2);
            int e3 = __shfl_sync(0xffffffffu, ei, k + 3);
            acc_half4(acc, &g_xe[e0 * HID + lane * 4]);
            acc_half4(acc, &g_xe[e1 * HID + lane * 4]);
            acc_half4(acc, &g_xe[e2 * HID + lane * 4]);
            acc_half4(acc, &g_xe[e3 * HID + lane * 4]);
        }
    }
    int rem = end - j;
    if (rem > 0) {
        int ei = (lane < rem) ? g_csr_ve[j + lane] : 0;
        for (int k = 0; k < rem; k++) {
            int e = __shfl_sync(0xffffffffu, ei, k);
            acc_half4(acc, &g_xe[e * HID + lane * 4]);
        }
    }
    float s = g_inv_cv[w];
    float4 x = *(const float4*)&g_x[w * HID + lane * 4];
    x.x += fmaxf(acc.x * s, 0.0f);
    x.y += fmaxf(acc.y * s, 0.0f);
    x.z += fmaxf(acc.z * s, 0.0f);
    x.w += fmaxf(acc.w * s, 0.0f);
    *(float4*)&g_x[w * HID + lane * 4] = x;
}

// ---------------- head: log_softmax(x @ W_out + b_out) ---------------------
__global__ void out_kernel(const float* __restrict__ Wo,
                           const float* __restrict__ bo,
                           float* __restrict__ out) {
    __shared__ float WsT[NOUT][HID];
    __shared__ float bs[NOUT];
    int t = threadIdx.x;
    for (int i = t; i < HID * NOUT; i += 256) {
        int k = i >> 4, o = i & 15;
        WsT[o][k] = Wo[i];
    }
    if (t < NOUT) bs[t] = bo[t];
    __syncthreads();

    int w = (blockIdx.x * 256 + t) >> 5;
    int lane = t & 31;
    if (w >= NN) return;
    float4 x = *(const float4*)&g_x[w * HID + lane * 4];

    float r[NOUT];
#pragma unroll
    for (int o = 0; o < NOUT; o++) {
        float4 wv = *(const float4*)&WsT[o][lane * 4];
        float p = x.x * wv.x + x.y * wv.y + x.z * wv.z + x.w * wv.w;
#pragma unroll
        for (int off = 16; off > 0; off >>= 1)
            p += __shfl_xor_sync(0xffffffffu, p, off);
        r[o] = p + bs[o];
    }

    float m = r[0];
#pragma unroll
    for (int o = 1; o < NOUT; o++) m = fmaxf(m, r[o]);
    float sum = 0.0f;
#pragma unroll
    for (int o = 0; o < NOUT; o++) sum += expf(r[o] - m);
    float lse = m + logf(sum);

    if (lane == 0) {
#pragma unroll
        for (int o = 0; o < NOUT; o++)
            out[w * NOUT + o] = r[o] - lse;
    }
}

// ---------------- launcher ----------------
extern "C" void kernel_launch(void* const* d_in, const int* in_sizes, int n_in,
                              void* d_out, int out_size) {
    const float* X     = (const float*)d_in[0];
    const int*   v_idx = (const int*)  d_in[1];
    const int*   e_idx = (const int*)  d_in[2];
    const float* W_enc = (const float*)d_in[3];
    const float* b_enc = (const float*)d_in[4];
    const float* ln_g  = (const float*)d_in[5];
    const float* ln_b  = (const float*)d_in[6];
    const float* Wt    = (const float*)d_in[7];
    const float* bt    = (const float*)d_in[8];
    const float* W_out = (const float*)d_in[9];
    const float* b_out = (const float*)d_in[10];
    float* out = (float*)d_out;

    zero_counts_kernel<<<(NN + 255) / 256, 256>>>();
    count_kernel<<<(PP + 255) / 256, 256>>>(v_idx, e_idx);
    inv_kernel<<<(NN + 255) / 256, 256>>>();
    int* off_e; cudaGetSymbolAddress((void**)&off_e, g_off_e);
    int* off_v; cudaGetSymbolAddress((void**)&off_v, g_off_v);
    int* cnt_e; cudaGetSymbolAddress((void**)&cnt_e, g_cnt_e);
    int* cnt_v; cudaGetSymbolAddress((void**)&cnt_v, g_cnt_v);
    int* cur_e; cudaGetSymbolAddress((void**)&cur_e, g_cur_e);
    int* cur_v; cudaGetSymbolAddress((void**)&cur_v, g_cur_v);
    scan_kernel<<<1, 1024>>>(cnt_e, off_e, cur_e, MM);
    scan_kernel<<<1, 1024>>>(cnt_v, off_v, cur_v, NN);
    fill_csr_kernel<<<(PP + 255) / 256, 256>>>(v_idx, e_idx);

    // fp16 conversions
    convert_x_kernel<<<(NN * CIN / 4 + 255) / 256, 256>>>(X);
    convert_w_kernel<<<(NLAYERS * HID * HID + 255) / 256, 256>>>(W_enc, Wt);

    // encoder (tensor core)
    enc_mma_kernel<<<(NN + 63) / 64, 256>>>(b_enc);

    const __half* wtT;
    { void* p; cudaGetSymbolAddress(&p, g_wtT); wtT = (const __half*)p; }

    for (int l = 0; l < NLAYERS; l++) {
        ln_mma_kernel<<<(NN + 63) / 64, 256>>>(ln_g + l * HID, ln_b + l * HID,
                                               wtT + l * HID * HID, bt + l * HID);
        gather_ve_kernel<<<(MM + 7) / 8, 256>>>();
        gather_ev_kernel<<<(NN + 7) / 8, 256>>>();
    }

    out_kernel<<<NN / 8, 256>>>(W_out, b_out, out);
}